// round 16
// baseline (speedup 1.0000x reference)
#include <cuda_runtime.h>

#define NN 50000
#define NE 1600000

// ---------------- device scratch (static: no runtime allocation) ----------------
__device__ __align__(16) float g_h[NN * 3 + 4];   // layer-1 accumulator (init = c1_bias)
__device__ __align__(16) float g_a2[NN * 4];      // layer-2 accumulator (init = c2_bias)
__device__ float g_W01[48];                       // factorized layer-1 weight: W_edge = e * W01  (layout c*3+k)
__device__ float g_W02[12];                       // factorized layer-2 weight (layout c*4+k)
__device__ int   g_fast1;                         // 1 iff all layer-1 MLP biases are exactly zero
__device__ int   g_fast2;
__device__ int   g_idx64;                         // 1 iff edge_index is int64

__device__ __forceinline__ float lrelu(float v) { return v > 0.0f ? v : 0.01f * v; }

// ---------------- dtype detection for edge_index ----------------
// int64 values < 50000 have zero high 32-bit words (little endian). For genuine
// int32 data the odd words are random indices, essentially never all zero.
__global__ void detect_kernel(const unsigned int* __restrict__ ei) {
    __shared__ unsigned int acc;
    if (threadIdx.x == 0) acc = 0u;
    __syncthreads();
    unsigned int v = 0u;
#pragma unroll
    for (int k = 0; k < 4; k++) {
        int t = threadIdx.x + k * 256;          // samples indices 1..2047 -> in-bounds for both dtypes
        v |= ei[2 * t + 1];
    }
    if (v) atomicOr(&acc, 1u);
    __syncthreads();
    if (threadIdx.x == 0) g_idx64 = (acc == 0u) ? 1 : 0;
}

// ---------------- factorization precompute + zero-bias check ----------------
// With b==0 and e>=0: lrelu(e*w) = e*lrelu(w), so the whole MLP is W(e) = e*W0.
__global__ void precompute_kernel(const float* __restrict__ w1, const float* __restrict__ b1,
                                  const float* __restrict__ w2, const float* __restrict__ b2,
                                  const float* __restrict__ w3, const float* __restrict__ b3,
                                  int M, int layer) {
    __shared__ float s1[16], s2[16];
    float* W0 = (layer == 0) ? g_W01 : g_W02;
    int t = threadIdx.x;
    if (t < 16) s1[t] = lrelu(w1[t]);
    __syncthreads();
    if (t < 16) {
        float p = 0.f;
#pragma unroll
        for (int i = 0; i < 16; i++) p += s1[i] * w2[i * 16 + t];
        s2[t] = lrelu(p);
    }
    __syncthreads();
    for (int m = t; m < M; m += blockDim.x) {
        float a = 0.f;
#pragma unroll
        for (int j = 0; j < 16; j++) a += s2[j] * w3[j * M + m];
        W0[m] = a;
    }
    if (t == 0) {
        int z = 1;
        for (int i = 0; i < 16; i++) { if (b1[i] != 0.f) z = 0; if (b2[i] != 0.f) z = 0; }
        for (int m = 0; m < M; m++) if (b3[m] != 0.f) z = 0;
        if (layer == 0) g_fast1 = z; else g_fast2 = z;
    }
}

// ---------------- init accumulators with biases ----------------
__global__ void init_kernel(const float* __restrict__ bias1, const float* __restrict__ bias2) {
    int i = blockIdx.x * blockDim.x + threadIdx.x;
    if (i >= NN) return;
    g_h[i * 3 + 0] = bias1[0];
    g_h[i * 3 + 1] = bias1[1];
    g_h[i * 3 + 2] = bias1[2];
    ((float4*)g_a2)[i] = make_float4(bias2[0], bias2[1], bias2[2], bias2[3]);
}

// ---------------- layer 1: per-edge message + scatter-add ----------------
__global__ void __launch_bounds__(256) edge1_kernel(
    const float* __restrict__ x, const int* __restrict__ ei, const float* __restrict__ ea,
    const float* __restrict__ w1, const float* __restrict__ b1,
    const float* __restrict__ w2, const float* __restrict__ b2,
    const float* __restrict__ w3, const float* __restrict__ b3) {
    // shared: factorized W0 + full slow-path weights
    __shared__ float sW0[48];
    __shared__ float sw[1120]; // [0:16) w1, [16:32) b1, [32:288) w2, [288:304) b2, [304:1072) w3, [1072:1120) b3
    __shared__ int sfast, sidx64;
    if (threadIdx.x == 0) { sfast = g_fast1; sidx64 = g_idx64; }
    for (int t = threadIdx.x; t < 48; t += 256) sW0[t] = g_W01[t];
    for (int t = threadIdx.x; t < 16; t += 256) { sw[t] = w1[t]; sw[16 + t] = b1[t]; sw[288 + t] = b2[t]; }
    for (int t = threadIdx.x; t < 256; t += 256) sw[32 + t] = w2[t];
    for (int t = threadIdx.x; t < 768; t += 256) sw[304 + t] = w3[t];
    for (int t = threadIdx.x; t < 48; t += 256) sw[1072 + t] = b3[t];
    __syncthreads();

    int i = blockIdx.x * blockDim.x + threadIdx.x;
    if (i >= NE) return;

    int src, dst;
    if (sidx64) { src = ei[2 * i]; dst = ei[2 * NE + 2 * i]; }
    else        { src = ei[i];     dst = ei[NE + i]; }
    float e = ea[i];

    const float4* xr = (const float4*)(x + (size_t)src * 16);
    float4 a = xr[0], b4 = xr[1], c4 = xr[2], d4 = xr[3];
    float xc[16] = {a.x, a.y, a.z, a.w, b4.x, b4.y, b4.z, b4.w,
                    c4.x, c4.y, c4.z, c4.w, d4.x, d4.y, d4.z, d4.w};

    float m0, m1, m2;
    if (sfast && e >= 0.f) {
        m0 = m1 = m2 = 0.f;
#pragma unroll
        for (int c = 0; c < 16; c++) {
            float xv = xc[c];
            m0 += xv * sW0[c * 3 + 0];
            m1 += xv * sW0[c * 3 + 1];
            m2 += xv * sW0[c * 3 + 2];
        }
        m0 *= e; m1 *= e; m2 *= e;
    } else {
        float h1[16];
#pragma unroll
        for (int q = 0; q < 16; q++) h1[q] = lrelu(e * sw[q] + sw[16 + q]);
        float h2[16];
#pragma unroll
        for (int j = 0; j < 16; j++) {
            float acc = sw[288 + j];
#pragma unroll
            for (int q = 0; q < 16; q++) acc += h1[q] * sw[32 + q * 16 + j];
            h2[j] = lrelu(acc);
        }
        m0 = m1 = m2 = 0.f;
#pragma unroll
        for (int c = 0; c < 16; c++) {
            float wv0 = sw[1072 + c * 3 + 0];
            float wv1 = sw[1072 + c * 3 + 1];
            float wv2 = sw[1072 + c * 3 + 2];
#pragma unroll
            for (int j = 0; j < 16; j++) {
                float hj = h2[j];
                wv0 += hj * sw[304 + j * 48 + c * 3 + 0];
                wv1 += hj * sw[304 + j * 48 + c * 3 + 1];
                wv2 += hj * sw[304 + j * 48 + c * 3 + 2];
            }
            m0 += xc[c] * wv0; m1 += xc[c] * wv1; m2 += xc[c] * wv2;
        }
    }
    float* hd = g_h + (size_t)dst * 3;
    atomicAdd(hd + 0, m0);
    atomicAdd(hd + 1, m1);
    atomicAdd(hd + 2, m2);
}

// ---------------- layer 2: reads relu(g_h[src]), scatter-add into g_a2 ----------------
__global__ void __launch_bounds__(256) edge2_kernel(
    const int* __restrict__ ei, const float* __restrict__ ea,
    const float* __restrict__ w1, const float* __restrict__ b1,
    const float* __restrict__ w2, const float* __restrict__ b2,
    const float* __restrict__ w3, const float* __restrict__ b3) {
    __shared__ float sW0[12];
    __shared__ float sw[508]; // [0:16) w1, [16:32) b1, [32:288) w2, [288:304) b2, [304:496) w3, [496:508) b3
    __shared__ int sfast, sidx64;
    if (threadIdx.x == 0) { sfast = g_fast2; sidx64 = g_idx64; }
    for (int t = threadIdx.x; t < 12; t += 256) sW0[t] = g_W02[t];
    for (int t = threadIdx.x; t < 16; t += 256) { sw[t] = w1[t]; sw[16 + t] = b1[t]; sw[288 + t] = b2[t]; }
    for (int t = threadIdx.x; t < 256; t += 256) sw[32 + t] = w2[t];
    for (int t = threadIdx.x; t < 192; t += 256) sw[304 + t] = w3[t];
    for (int t = threadIdx.x; t < 12; t += 256) sw[496 + t] = b3[t];
    __syncthreads();

    int i = blockIdx.x * blockDim.x + threadIdx.x;
    if (i >= NE) return;

    int src, dst;
    if (sidx64) { src = ei[2 * i]; dst = ei[2 * NE + 2 * i]; }
    else        { src = ei[i];     dst = ei[NE + i]; }
    float e = ea[i];

    const float* hp = g_h + (size_t)src * 3;
    float hc0 = fmaxf(hp[0], 0.f);
    float hc1 = fmaxf(hp[1], 0.f);
    float hc2 = fmaxf(hp[2], 0.f);

    float m[4];
    if (sfast && e >= 0.f) {
#pragma unroll
        for (int k = 0; k < 4; k++)
            m[k] = e * (hc0 * sW0[k] + hc1 * sW0[4 + k] + hc2 * sW0[8 + k]);
    } else {
        float h1[16];
#pragma unroll
        for (int q = 0; q < 16; q++) h1[q] = lrelu(e * sw[q] + sw[16 + q]);
        float h2[16];
#pragma unroll
        for (int j = 0; j < 16; j++) {
            float acc = sw[288 + j];
#pragma unroll
            for (int q = 0; q < 16; q++) acc += h1[q] * sw[32 + q * 16 + j];
            h2[j] = lrelu(acc);
        }
        float hc[3] = {hc0, hc1, hc2};
#pragma unroll
        for (int k = 0; k < 4; k++) m[k] = 0.f;
#pragma unroll
        for (int c = 0; c < 3; c++) {
#pragma unroll
            for (int k = 0; k < 4; k++) {
                float wv = sw[496 + c * 4 + k];
#pragma unroll
                for (int j = 0; j < 16; j++) wv += h2[j] * sw[304 + j * 12 + c * 4 + k];
                m[k] += hc[c] * wv;
            }
        }
    }
    float* ad = g_a2 + (size_t)dst * 4;
    atomicAdd(ad + 0, m[0]);
    atomicAdd(ad + 1, m[1]);
    atomicAdd(ad + 2, m[2]);
    atomicAdd(ad + 3, m[3]);
}

// ---------------- epilogue: relu + softmax per node ----------------
__global__ void final_kernel(float* __restrict__ out) {
    int n = blockIdx.x * blockDim.x + threadIdx.x;
    if (n >= NN) return;
    float4 v = ((const float4*)g_a2)[n];
    v.x = fmaxf(v.x, 0.f); v.y = fmaxf(v.y, 0.f);
    v.z = fmaxf(v.z, 0.f); v.w = fmaxf(v.w, 0.f);
    float mx = fmaxf(fmaxf(v.x, v.y), fmaxf(v.z, v.w));
    float e0 = expf(v.x - mx), e1 = expf(v.y - mx), e2 = expf(v.z - mx), e3 = expf(v.w - mx);
    float inv = 1.f / (e0 + e1 + e2 + e3);
    ((float4*)out)[n] = make_float4(e0 * inv, e1 * inv, e2 * inv, e3 * inv);
}

extern "C" void kernel_launch(void* const* d_in, const int* in_sizes, int n_in,
                              void* d_out, int out_size) {
    const float* x     = (const float*)d_in[0];
    const int*   ei    = (const int*)d_in[1];   // dtype resolved on device
    const float* ea    = (const float*)d_in[2];
    const float* c1_w1 = (const float*)d_in[3];
    const float* c1_b1 = (const float*)d_in[4];
    const float* c1_w2 = (const float*)d_in[5];
    const float* c1_b2 = (const float*)d_in[6];
    const float* c1_w3 = (const float*)d_in[7];
    const float* c1_b3 = (const float*)d_in[8];
    const float* c1_bs = (const float*)d_in[9];
    const float* c2_w1 = (const float*)d_in[10];
    const float* c2_b1 = (const float*)d_in[11];
    const float* c2_w2 = (const float*)d_in[12];
    const float* c2_b2 = (const float*)d_in[13];
    const float* c2_w3 = (const float*)d_in[14];
    const float* c2_b3 = (const float*)d_in[15];
    const float* c2_bs = (const float*)d_in[16];
    float* out = (float*)d_out;

    detect_kernel<<<1, 256>>>((const unsigned int*)d_in[1]);
    precompute_kernel<<<1, 64>>>(c1_w1, c1_b1, c1_w2, c1_b2, c1_w3, c1_b3, 48, 0);
    precompute_kernel<<<1, 64>>>(c2_w1, c2_b1, c2_w2, c2_b2, c2_w3, c2_b3, 12, 1);
    init_kernel<<<(NN + 255) / 256, 256>>>(c1_bs, c2_bs);
    edge1_kernel<<<NE / 256, 256>>>(x, ei, ea, c1_w1, c1_b1, c1_w2, c1_b2, c1_w3, c1_b3);
    edge2_kernel<<<NE / 256, 256>>>(ei, ea, c2_w1, c2_b1, c2_w2, c2_b2, c2_w3, c2_b3);
    final_kernel<<<(NN + 255) / 256, 256>>>(out);
}

// round 17
// speedup vs baseline: 1.3812x; 1.3812x over previous
#include <cuda_runtime.h>

#define NN 50000
#define NE 1600000

// ---------------- device scratch (static: no runtime allocation) ----------------
__device__ __align__(16) float g_h[NN * 4];       // layer-1 accumulator, padded to 4 (pad lane unused)
__device__ __align__(16) float g_a2[NN * 4];      // layer-2 accumulator (init = c2_bias)
__device__ float g_W01[96];                       // factorized layer-1: [sign][c*3+k], sign0=e>=0, sign1=e<0
__device__ float g_W02[24];                       // factorized layer-2: [sign][c*4+k]
__device__ int   g_fast1;                         // 1 iff all layer-1 MLP biases are exactly zero
__device__ int   g_fast2;
__device__ int   g_idx64;                         // 1 iff edge_index is int64

__device__ __forceinline__ float lrelu(float v) { return v > 0.0f ? v : 0.01f * v; }

// one REDG.128 instead of 3-4 REDG.32
__device__ __forceinline__ void red_add_v4(float* addr, float a, float b, float c, float d) {
    asm volatile("red.global.add.v4.f32 [%0], {%1,%2,%3,%4};"
                 :: "l"(addr), "f"(a), "f"(b), "f"(c), "f"(d) : "memory");
}

// ---------------- dtype detection for edge_index ----------------
__global__ void detect_kernel(const unsigned int* __restrict__ ei) {
    __shared__ unsigned int acc;
    if (threadIdx.x == 0) acc = 0u;
    __syncthreads();
    unsigned int v = 0u;
#pragma unroll
    for (int k = 0; k < 4; k++) {
        int t = threadIdx.x + k * 256;
        v |= ei[2 * t + 1];
    }
    if (v) atomicOr(&acc, 1u);
    __syncthreads();
    if (threadIdx.x == 0) g_idx64 = (acc == 0u) ? 1 : 0;
}

// ---------------- factorization precompute (both signs) + zero-bias check ----------------
// b==0:  e>=0: lrelu(e*w) = e*lrelu(w)
//        e< 0: lrelu(e*w) = e*(-lrelu(-w))
// so the whole MLP collapses to W(e) = e * W0[sign(e)].
__global__ void precompute_kernel(const float* __restrict__ w1, const float* __restrict__ b1,
                                  const float* __restrict__ w2, const float* __restrict__ b2,
                                  const float* __restrict__ w3, const float* __restrict__ b3,
                                  int M, int layer) {
    __shared__ float s1[2][16], s2[2][16];
    float* W0 = (layer == 0) ? g_W01 : g_W02;
    int t = threadIdx.x;
    if (t < 16) {
        s1[0][t] = lrelu(w1[t]);
        s1[1][t] = -lrelu(-w1[t]);
    }
    __syncthreads();
    if (t < 32) {
        int sg = t >> 4, j = t & 15;
        float p = 0.f;
#pragma unroll
        for (int i = 0; i < 16; i++) p += s1[sg][i] * w2[i * 16 + j];
        s2[sg][j] = (sg == 0) ? lrelu(p) : -lrelu(-p);
    }
    __syncthreads();
    for (int sg = 0; sg < 2; sg++) {
        for (int m = t; m < M; m += blockDim.x) {
            float a = 0.f;
#pragma unroll
            for (int j = 0; j < 16; j++) a += s2[sg][j] * w3[j * M + m];
            W0[sg * M + m] = a;
        }
    }
    if (t == 0) {
        int z = 1;
        for (int i = 0; i < 16; i++) { if (b1[i] != 0.f) z = 0; if (b2[i] != 0.f) z = 0; }
        for (int m = 0; m < M; m++) if (b3[m] != 0.f) z = 0;
        if (layer == 0) g_fast1 = z; else g_fast2 = z;
    }
}

// ---------------- init accumulators with biases ----------------
__global__ void init_kernel(const float* __restrict__ bias1, const float* __restrict__ bias2) {
    int i = blockIdx.x * blockDim.x + threadIdx.x;
    if (i >= NN) return;
    ((float4*)g_h)[i]  = make_float4(bias1[0], bias1[1], bias1[2], 0.f);
    ((float4*)g_a2)[i] = make_float4(bias2[0], bias2[1], bias2[2], bias2[3]);
}

// ---------------- layer 1: per-edge message + vectorized scatter-add ----------------
__global__ void __launch_bounds__(256) edge1_kernel(
    const float* __restrict__ x, const int* __restrict__ ei, const float* __restrict__ ea,
    const float* __restrict__ w1, const float* __restrict__ b1,
    const float* __restrict__ w2, const float* __restrict__ b2,
    const float* __restrict__ w3, const float* __restrict__ b3) {
    __shared__ float sW0[96];
    __shared__ float sw[1120]; // [0:16) w1, [16:32) b1, [32:288) w2, [288:304) b2, [304:1072) w3, [1072:1120) b3
    __shared__ int sfast, sidx64;
    if (threadIdx.x == 0) { sfast = g_fast1; sidx64 = g_idx64; }
    for (int t = threadIdx.x; t < 96; t += 256) sW0[t] = g_W01[t];
    __syncthreads();
    if (!sfast) {  // block-uniform branch; slow-path weights loaded only when needed
        for (int t = threadIdx.x; t < 16; t += 256) { sw[t] = w1[t]; sw[16 + t] = b1[t]; sw[288 + t] = b2[t]; }
        for (int t = threadIdx.x; t < 256; t += 256) sw[32 + t] = w2[t];
        for (int t = threadIdx.x; t < 768; t += 256) sw[304 + t] = w3[t];
        for (int t = threadIdx.x; t < 48; t += 256) sw[1072 + t] = b3[t];
        __syncthreads();
    }

    int i = blockIdx.x * blockDim.x + threadIdx.x;
    if (i >= NE) return;

    int src, dst;
    if (sidx64) { src = ei[2 * i]; dst = ei[2 * NE + 2 * i]; }
    else        { src = ei[i];     dst = ei[NE + i]; }
    float e = ea[i];

    const float4* xr = (const float4*)(x + (size_t)src * 16);
    float4 a = xr[0], b4 = xr[1], c4 = xr[2], d4 = xr[3];
    float xc[16] = {a.x, a.y, a.z, a.w, b4.x, b4.y, b4.z, b4.w,
                    c4.x, c4.y, c4.z, c4.w, d4.x, d4.y, d4.z, d4.w};

    float m0, m1, m2;
    if (sfast) {
        const float* W = sW0 + (e >= 0.f ? 0 : 48);
        m0 = m1 = m2 = 0.f;
#pragma unroll
        for (int c = 0; c < 16; c++) {
            float xv = xc[c];
            m0 += xv * W[c * 3 + 0];
            m1 += xv * W[c * 3 + 1];
            m2 += xv * W[c * 3 + 2];
        }
        m0 *= e; m1 *= e; m2 *= e;
    } else {
        float h1[16];
#pragma unroll
        for (int q = 0; q < 16; q++) h1[q] = lrelu(e * sw[q] + sw[16 + q]);
        float h2[16];
#pragma unroll
        for (int j = 0; j < 16; j++) {
            float acc = sw[288 + j];
#pragma unroll
            for (int q = 0; q < 16; q++) acc += h1[q] * sw[32 + q * 16 + j];
            h2[j] = lrelu(acc);
        }
        m0 = m1 = m2 = 0.f;
#pragma unroll
        for (int c = 0; c < 16; c++) {
            float wv0 = sw[1072 + c * 3 + 0];
            float wv1 = sw[1072 + c * 3 + 1];
            float wv2 = sw[1072 + c * 3 + 2];
#pragma unroll
            for (int j = 0; j < 16; j++) {
                float hj = h2[j];
                wv0 += hj * sw[304 + j * 48 + c * 3 + 0];
                wv1 += hj * sw[304 + j * 48 + c * 3 + 1];
                wv2 += hj * sw[304 + j * 48 + c * 3 + 2];
            }
            m0 += xc[c] * wv0; m1 += xc[c] * wv1; m2 += xc[c] * wv2;
        }
    }
    red_add_v4(g_h + (size_t)dst * 4, m0, m1, m2, 0.f);
}

// ---------------- layer 2: reads relu(g_h[src]) as LDG.128, vectorized scatter-add ----------------
__global__ void __launch_bounds__(256) edge2_kernel(
    const int* __restrict__ ei, const float* __restrict__ ea,
    const float* __restrict__ w1, const float* __restrict__ b1,
    const float* __restrict__ w2, const float* __restrict__ b2,
    const float* __restrict__ w3, const float* __restrict__ b3) {
    __shared__ float sW0[24];
    __shared__ float sw[508]; // [0:16) w1, [16:32) b1, [32:288) w2, [288:304) b2, [304:496) w3, [496:508) b3
    __shared__ int sfast, sidx64;
    if (threadIdx.x == 0) { sfast = g_fast2; sidx64 = g_idx64; }
    for (int t = threadIdx.x; t < 24; t += 256) sW0[t] = g_W02[t];
    __syncthreads();
    if (!sfast) {
        for (int t = threadIdx.x; t < 16; t += 256) { sw[t] = w1[t]; sw[16 + t] = b1[t]; sw[288 + t] = b2[t]; }
        for (int t = threadIdx.x; t < 256; t += 256) sw[32 + t] = w2[t];
        for (int t = threadIdx.x; t < 192; t += 256) sw[304 + t] = w3[t];
        for (int t = threadIdx.x; t < 12; t += 256) sw[496 + t] = b3[t];
        __syncthreads();
    }

    int i = blockIdx.x * blockDim.x + threadIdx.x;
    if (i >= NE) return;

    int src, dst;
    if (sidx64) { src = ei[2 * i]; dst = ei[2 * NE + 2 * i]; }
    else        { src = ei[i];     dst = ei[NE + i]; }
    float e = ea[i];

    float4 hv = *((const float4*)(g_h + (size_t)src * 4));
    float hc0 = fmaxf(hv.x, 0.f);
    float hc1 = fmaxf(hv.y, 0.f);
    float hc2 = fmaxf(hv.z, 0.f);

    float m[4];
    if (sfast) {
        const float* W = sW0 + (e >= 0.f ? 0 : 12);
#pragma unroll
        for (int k = 0; k < 4; k++)
            m[k] = e * (hc0 * W[k] + hc1 * W[4 + k] + hc2 * W[8 + k]);
    } else {
        float h1[16];
#pragma unroll
        for (int q = 0; q < 16; q++) h1[q] = lrelu(e * sw[q] + sw[16 + q]);
        float h2[16];
#pragma unroll
        for (int j = 0; j < 16; j++) {
            float acc = sw[288 + j];
#pragma unroll
            for (int q = 0; q < 16; q++) acc += h1[q] * sw[32 + q * 16 + j];
            h2[j] = lrelu(acc);
        }
        float hc[3] = {hc0, hc1, hc2};
#pragma unroll
        for (int k = 0; k < 4; k++) m[k] = 0.f;
#pragma unroll
        for (int c = 0; c < 3; c++) {
#pragma unroll
            for (int k = 0; k < 4; k++) {
                float wv = sw[496 + c * 4 + k];
#pragma unroll
                for (int j = 0; j < 16; j++) wv += h2[j] * sw[304 + j * 12 + c * 4 + k];
                m[k] += hc[c] * wv;
            }
        }
    }
    red_add_v4(g_a2 + (size_t)dst * 4, m[0], m[1], m[2], m[3]);
}

// ---------------- epilogue: relu + softmax per node ----------------
__global__ void final_kernel(float* __restrict__ out) {
    int n = blockIdx.x * blockDim.x + threadIdx.x;
    if (n >= NN) return;
    float4 v = ((const float4*)g_a2)[n];
    v.x = fmaxf(v.x, 0.f); v.y = fmaxf(v.y, 0.f);
    v.z = fmaxf(v.z, 0.f); v.w = fmaxf(v.w, 0.f);
    float mx = fmaxf(fmaxf(v.x, v.y), fmaxf(v.z, v.w));
    float e0 = expf(v.x - mx), e1 = expf(v.y - mx), e2 = expf(v.z - mx), e3 = expf(v.w - mx);
    float inv = 1.f / (e0 + e1 + e2 + e3);
    ((float4*)out)[n] = make_float4(e0 * inv, e1 * inv, e2 * inv, e3 * inv);
}

extern "C" void kernel_launch(void* const* d_in, const int* in_sizes, int n_in,
                              void* d_out, int out_size) {
    const float* x     = (const float*)d_in[0];
    const int*   ei    = (const int*)d_in[1];   // dtype resolved on device
    const float* ea    = (const float*)d_in[2];
    const float* c1_w1 = (const float*)d_in[3];
    const float* c1_b1 = (const float*)d_in[4];
    const float* c1_w2 = (const float*)d_in[5];
    const float* c1_b2 = (const float*)d_in[6];
    const float* c1_w3 = (const float*)d_in[7];
    const float* c1_b3 = (const float*)d_in[8];
    const float* c1_bs = (const float*)d_in[9];
    const float* c2_w1 = (const float*)d_in[10];
    const float* c2_b1 = (const float*)d_in[11];
    const float* c2_w2 = (const float*)d_in[12];
    const float* c2_b2 = (const float*)d_in[13];
    const float* c2_w3 = (const float*)d_in[14];
    const float* c2_b3 = (const float*)d_in[15];
    const float* c2_bs = (const float*)d_in[16];
    float* out = (float*)d_out;

    detect_kernel<<<1, 256>>>((const unsigned int*)d_in[1]);
    precompute_kernel<<<1, 64>>>(c1_w1, c1_b1, c1_w2, c1_b2, c1_w3, c1_b3, 48, 0);
    precompute_kernel<<<1, 64>>>(c2_w1, c2_b1, c2_w2, c2_b2, c2_w3, c2_b3, 12, 1);
    init_kernel<<<(NN + 255) / 256, 256>>>(c1_bs, c2_bs);
    edge1_kernel<<<NE / 256, 256>>>(x, ei, ea, c1_w1, c1_b1, c1_w2, c1_b2, c1_w3, c1_b3);
    edge2_kernel<<<NE / 256, 256>>>(ei, ea, c2_w1, c2_b1, c2_w2, c2_b2, c2_w3, c2_b3);
    final_kernel<<<(NN + 255) / 256, 256>>>(out);
}